// round 1
// baseline (speedup 1.0000x reference)
#include <cuda_runtime.h>

#define CIN  1024
#define COUT 1024

// Dense W scratch (allocation-free: __device__ global).
__device__ float g_W[COUT * CIN];

// ---------------------------------------------------------------------------
// Kernel 1: zero W (vectorized)
// ---------------------------------------------------------------------------
__global__ void zero_W_kernel() {
    int i = blockIdx.x * blockDim.x + threadIdx.x;
    reinterpret_cast<float4*>(g_W)[i] = make_float4(0.f, 0.f, 0.f, 0.f);
}

// ---------------------------------------------------------------------------
// Kernel 2: scatter-add values into W (coalesce semantics: duplicates sum)
// indices layout: [2, nnz] -> rows at idx[0..nnz), cols at idx[nnz..2*nnz)
// ---------------------------------------------------------------------------
__global__ void scatter_W_kernel(const float* __restrict__ vals,
                                 const int* __restrict__ idx, int nnz) {
    int i = blockIdx.x * blockDim.x + threadIdx.x;
    if (i < nnz) {
        int r = idx[i];
        int c = idx[nnz + i];
        atomicAdd(&g_W[r * CIN + c], vals[i]);
    }
}

// ---------------------------------------------------------------------------
// Kernel 3: SGEMM  C[m,n] = sum_k A[m,k] * W[n,k]
// A: [M, CIN] row-major (K-contiguous), W: [COUT, CIN] row-major (K-contiguous)
// BM=128, BN=128, BK=16, 256 threads, 8x8 microtile, double-buffered SMEM.
// ---------------------------------------------------------------------------
#define BM 128
#define BN 128
#define BK 16
#define LDS_STRIDE (BM + 4)   // 132: pad to reduce transpose-store conflicts,
                              // keeps float4 alignment (132 % 4 == 0)

__global__ __launch_bounds__(256, 2)
void sgemm_kernel(const float* __restrict__ A, float* __restrict__ C) {
    __shared__ float As[2][BK * LDS_STRIDE];
    __shared__ float Bs[2][BK * LDS_STRIDE];

    const int tid = threadIdx.x;
    const int tx  = tid & 15;   // N direction (0..15)
    const int ty  = tid >> 4;   // M direction (0..15)

    const float* __restrict__ Ab = A   + (size_t)blockIdx.y * BM * CIN;
    const float* __restrict__ Bb = g_W + (size_t)blockIdx.x * BN * CIN;
    float* __restrict__       Cb = C   + (size_t)blockIdx.y * BM * COUT
                                       + (size_t)blockIdx.x * BN;

    // Global->SMEM load mapping: 512 float4 per tile (128 rows x 4 float4),
    // each thread handles 2: (row = f>>2, kvec = f&3), f = tid and tid+256.
    const int lrow0 = tid >> 2;        // 0..63
    const int lrow1 = lrow0 + 64;      // 64..127
    const int lk    = (tid & 3) * 4;   // k offset within tile: 0,4,8,12

    float acc[8][8];
#pragma unroll
    for (int i = 0; i < 8; i++)
#pragma unroll
        for (int j = 0; j < 8; j++) acc[i][j] = 0.f;

    float4 pa0, pa1, pb0, pb1;

    // Prologue: load k-tile 0 into registers, then SMEM buf 0
    pa0 = *(const float4*)(Ab + (size_t)lrow0 * CIN + lk);
    pa1 = *(const float4*)(Ab + (size_t)lrow1 * CIN + lk);
    pb0 = *(const float4*)(Bb + (size_t)lrow0 * CIN + lk);
    pb1 = *(const float4*)(Bb + (size_t)lrow1 * CIN + lk);

    {
        float* as = As[0]; float* bs = Bs[0];
        as[(lk + 0) * LDS_STRIDE + lrow0] = pa0.x;
        as[(lk + 1) * LDS_STRIDE + lrow0] = pa0.y;
        as[(lk + 2) * LDS_STRIDE + lrow0] = pa0.z;
        as[(lk + 3) * LDS_STRIDE + lrow0] = pa0.w;
        as[(lk + 0) * LDS_STRIDE + lrow1] = pa1.x;
        as[(lk + 1) * LDS_STRIDE + lrow1] = pa1.y;
        as[(lk + 2) * LDS_STRIDE + lrow1] = pa1.z;
        as[(lk + 3) * LDS_STRIDE + lrow1] = pa1.w;
        bs[(lk + 0) * LDS_STRIDE + lrow0] = pb0.x;
        bs[(lk + 1) * LDS_STRIDE + lrow0] = pb0.y;
        bs[(lk + 2) * LDS_STRIDE + lrow0] = pb0.z;
        bs[(lk + 3) * LDS_STRIDE + lrow0] = pb0.w;
        bs[(lk + 0) * LDS_STRIDE + lrow1] = pb1.x;
        bs[(lk + 1) * LDS_STRIDE + lrow1] = pb1.y;
        bs[(lk + 2) * LDS_STRIDE + lrow1] = pb1.z;
        bs[(lk + 3) * LDS_STRIDE + lrow1] = pb1.w;
    }
    __syncthreads();

    int buf = 0;
#pragma unroll 1
    for (int k0 = BK; k0 <= CIN; k0 += BK) {
        // Prefetch next k-tile into registers (overlaps with compute below)
        if (k0 < CIN) {
            pa0 = *(const float4*)(Ab + (size_t)lrow0 * CIN + k0 + lk);
            pa1 = *(const float4*)(Ab + (size_t)lrow1 * CIN + k0 + lk);
            pb0 = *(const float4*)(Bb + (size_t)lrow0 * CIN + k0 + lk);
            pb1 = *(const float4*)(Bb + (size_t)lrow1 * CIN + k0 + lk);
        }

        // Compute on current buffer
        const float* as = As[buf];
        const float* bs = Bs[buf];
#pragma unroll
        for (int kk = 0; kk < BK; kk++) {
            float a[8], b[8];
            *(float4*)(a + 0) = *(const float4*)(as + kk * LDS_STRIDE + ty * 8 + 0);
            *(float4*)(a + 4) = *(const float4*)(as + kk * LDS_STRIDE + ty * 8 + 4);
            *(float4*)(b + 0) = *(const float4*)(bs + kk * LDS_STRIDE + tx * 8 + 0);
            *(float4*)(b + 4) = *(const float4*)(bs + kk * LDS_STRIDE + tx * 8 + 4);
#pragma unroll
            for (int i = 0; i < 8; i++)
#pragma unroll
                for (int j = 0; j < 8; j++)
                    acc[i][j] += a[i] * b[j];
        }

        // Store prefetched tile into the other buffer
        if (k0 < CIN) {
            buf ^= 1;
            float* as2 = As[buf]; float* bs2 = Bs[buf];
            as2[(lk + 0) * LDS_STRIDE + lrow0] = pa0.x;
            as2[(lk + 1) * LDS_STRIDE + lrow0] = pa0.y;
            as2[(lk + 2) * LDS_STRIDE + lrow0] = pa0.z;
            as2[(lk + 3) * LDS_STRIDE + lrow0] = pa0.w;
            as2[(lk + 0) * LDS_STRIDE + lrow1] = pa1.x;
            as2[(lk + 1) * LDS_STRIDE + lrow1] = pa1.y;
            as2[(lk + 2) * LDS_STRIDE + lrow1] = pa1.z;
            as2[(lk + 3) * LDS_STRIDE + lrow1] = pa1.w;
            bs2[(lk + 0) * LDS_STRIDE + lrow0] = pb0.x;
            bs2[(lk + 1) * LDS_STRIDE + lrow0] = pb0.y;
            bs2[(lk + 2) * LDS_STRIDE + lrow0] = pb0.z;
            bs2[(lk + 3) * LDS_STRIDE + lrow0] = pb0.w;
            bs2[(lk + 0) * LDS_STRIDE + lrow1] = pb1.x;
            bs2[(lk + 1) * LDS_STRIDE + lrow1] = pb1.y;
            bs2[(lk + 2) * LDS_STRIDE + lrow1] = pb1.z;
            bs2[(lk + 3) * LDS_STRIDE + lrow1] = pb1.w;
            __syncthreads();
        }
    }

    // Epilogue: coalesced float4 stores
#pragma unroll
    for (int i = 0; i < 8; i++) {
        float* crow = Cb + (size_t)(ty * 8 + i) * COUT + tx * 8;
        *(float4*)(crow + 0) = make_float4(acc[i][0], acc[i][1], acc[i][2], acc[i][3]);
        *(float4*)(crow + 4) = make_float4(acc[i][4], acc[i][5], acc[i][6], acc[i][7]);
    }
}

// ---------------------------------------------------------------------------
extern "C" void kernel_launch(void* const* d_in, const int* in_sizes, int n_in,
                              void* d_out, int out_size) {
    const float* x    = (const float*)d_in[0];   // [4, 4096, CIN] fp32
    const float* vals = (const float*)d_in[1];   // [nnz] fp32
    const int*   idx  = (const int*)d_in[2];     // [2, nnz] int32
    float* out = (float*)d_out;                  // [4, 4096, COUT] fp32

    const int nnz = in_sizes[1];
    const int M   = in_sizes[0] / CIN;           // 16384

    // 1) W = 0
    zero_W_kernel<<<(COUT * CIN / 4) / 256, 256>>>();
    // 2) scatter-add (coalesce duplicates)
    scatter_W_kernel<<<(nnz + 255) / 256, 256>>>(vals, idx, nnz);
    // 3) out = x @ W^T
    dim3 grid(COUT / BN, M / BM);
    sgemm_kernel<<<grid, 256>>>(x, out);
}

// round 3
// speedup vs baseline: 2.1395x; 2.1395x over previous
#include <cuda_runtime.h>
#include <cuda_bf16.h>
#include <cstdint>

#define CIN  1024
#define COUT 1024
#define MAX_M 16384

// ---------------- device global scratch (allocation-free) ----------------
__device__ float         g_W[COUT * CIN];        // densified fp32 W
__device__ __nv_bfloat16 g_Whi[COUT * CIN];
__device__ __nv_bfloat16 g_Wlo[COUT * CIN];
__device__ __nv_bfloat16 g_Ahi[MAX_M * CIN];
__device__ __nv_bfloat16 g_Alo[MAX_M * CIN];

// ---------------- PTX helpers (all vanilla sm_80/75 — no 'a' features) ---
__device__ __forceinline__ uint32_t smem_u32(const void* p) {
    uint32_t a;
    asm("{ .reg .u64 t; cvta.to.shared.u64 t, %1; cvt.u32.u64 %0, t; }"
        : "=r"(a) : "l"(p));
    return a;
}
__device__ __forceinline__ void cpa16(uint32_t dst, const void* src) {
    asm volatile("cp.async.cg.shared.global [%0], [%1], 16;" :: "r"(dst), "l"(src));
}
__device__ __forceinline__ void cp_commit() {
    asm volatile("cp.async.commit_group;" ::: "memory");
}
template<int N> __device__ __forceinline__ void cp_wait() {
    asm volatile("cp.async.wait_group %0;" :: "n"(N) : "memory");
}
__device__ __forceinline__ void ldsm_x4(uint32_t& r0, uint32_t& r1, uint32_t& r2,
                                        uint32_t& r3, uint32_t addr) {
    asm volatile("ldmatrix.sync.aligned.m8n8.x4.shared.b16 {%0,%1,%2,%3}, [%4];"
                 : "=r"(r0), "=r"(r1), "=r"(r2), "=r"(r3) : "r"(addr));
}
__device__ __forceinline__ void ldsm_x2(uint32_t& r0, uint32_t& r1, uint32_t addr) {
    asm volatile("ldmatrix.sync.aligned.m8n8.x2.shared.b16 {%0,%1}, [%2];"
                 : "=r"(r0), "=r"(r1) : "r"(addr));
}
__device__ __forceinline__ void mma_bf16(float* c, const uint32_t* a, const uint32_t* b) {
    asm volatile(
        "mma.sync.aligned.m16n8k16.row.col.f32.bf16.bf16.f32 "
        "{%0,%1,%2,%3}, {%4,%5,%6,%7}, {%8,%9}, {%0,%1,%2,%3};"
        : "+f"(c[0]), "+f"(c[1]), "+f"(c[2]), "+f"(c[3])
        : "r"(a[0]), "r"(a[1]), "r"(a[2]), "r"(a[3]), "r"(b[0]), "r"(b[1]));
}

// ---------------- preprocessing kernels ----------------
__global__ void zero_W_kernel() {
    int i = blockIdx.x * blockDim.x + threadIdx.x;
    reinterpret_cast<float4*>(g_W)[i] = make_float4(0.f, 0.f, 0.f, 0.f);
}

__global__ void scatter_W_kernel(const float* __restrict__ vals,
                                 const int* __restrict__ idx, int nnz) {
    int i = blockIdx.x * blockDim.x + threadIdx.x;
    if (i < nnz) {
        int r = idx[i];
        int c = idx[nnz + i];
        atomicAdd(&g_W[r * CIN + c], vals[i]);
    }
}

// fp32 -> (bf16 hi, bf16 lo) split, 4 elems per thread
__device__ __forceinline__ void split4(const float4 v,
                                       __nv_bfloat16* hi, __nv_bfloat16* lo, size_t i4) {
    __nv_bfloat16 h0 = __float2bfloat16(v.x);
    __nv_bfloat16 h1 = __float2bfloat16(v.y);
    __nv_bfloat16 h2 = __float2bfloat16(v.z);
    __nv_bfloat16 h3 = __float2bfloat16(v.w);
    __nv_bfloat16 l0 = __float2bfloat16(v.x - __bfloat162float(h0));
    __nv_bfloat16 l1 = __float2bfloat16(v.y - __bfloat162float(h1));
    __nv_bfloat16 l2 = __float2bfloat16(v.z - __bfloat162float(h2));
    __nv_bfloat16 l3 = __float2bfloat16(v.w - __bfloat162float(h3));
    __nv_bfloat162 H0; H0.x = h0; H0.y = h1;
    __nv_bfloat162 H1; H1.x = h2; H1.y = h3;
    __nv_bfloat162 L0; L0.x = l0; L0.y = l1;
    __nv_bfloat162 L1; L1.x = l2; L1.y = l3;
    reinterpret_cast<__nv_bfloat162*>(hi)[2 * i4 + 0] = H0;
    reinterpret_cast<__nv_bfloat162*>(hi)[2 * i4 + 1] = H1;
    reinterpret_cast<__nv_bfloat162*>(lo)[2 * i4 + 0] = L0;
    reinterpret_cast<__nv_bfloat162*>(lo)[2 * i4 + 1] = L1;
}

__global__ void convert_A_kernel(const float* __restrict__ x, int n4) {
    int i = blockIdx.x * blockDim.x + threadIdx.x;
    if (i < n4) split4(reinterpret_cast<const float4*>(x)[i], g_Ahi, g_Alo, i);
}

__global__ void convert_W_kernel() {
    int i = blockIdx.x * blockDim.x + threadIdx.x;   // COUT*CIN/4 threads
    split4(reinterpret_cast<const float4*>(g_W)[i], g_Whi, g_Wlo, i);
}

// ---------------- bf16 mma.sync GEMM (3-split for fp32 accuracy) ----------
// out[m,n] = sum_k (Ahi+Alo)[m,k]*(Whi+Wlo)[n,k], dropping the lo*lo term.
// BM=BN=128, BK=32 bf16, 256 thr = 8 warps in 2(M)x4(N), warp tile 64x32.
#define BK 32
#define ROWB 80                 // SMEM row stride bytes (32 bf16 + 8 pad)
#define TILE_BYTES (128 * ROWB) // 10240 per operand
#define STAGE_BYTES (2 * TILE_BYTES)
#define NSTAGE 4
#define SMEM_TOTAL (NSTAGE * STAGE_BYTES)   // 81920
#define K_ITERS 96              // 3 phases * (1024/32)

__global__ void __launch_bounds__(256)
gemm_bf16x3_kernel(float* __restrict__ out) {
    extern __shared__ char smem_raw[];
    const uint32_t sbase = smem_u32(smem_raw);
    const int tid  = threadIdx.x;
    const int lane = tid & 31;
    const int wid  = tid >> 5;
    const int wm   = (wid & 1) * 64;   // warp M offset in tile
    const int wn   = (wid >> 1) * 32;  // warp N offset in tile
    const int m0   = blockIdx.y * 128;
    const int n0   = blockIdx.x * 128;

    float acc[4][4][4];
#pragma unroll
    for (int mi = 0; mi < 4; mi++)
#pragma unroll
        for (int ni = 0; ni < 4; ni++)
#pragma unroll
            for (int q = 0; q < 4; q++) acc[mi][ni][q] = 0.f;

    auto load_stage = [&](int j) {
        const int ph = j >> 5;                  // 0: hi*hi, 1: lo*hi, 2: hi*lo
        const int kk = (j & 31) * BK;
        const __nv_bfloat16* A = (ph == 1) ? g_Alo : g_Ahi;
        const __nv_bfloat16* W = (ph == 2) ? g_Wlo : g_Whi;
        const uint32_t aS = sbase + (j & 3) * STAGE_BYTES;
        const uint32_t bS = aS + TILE_BYTES;
#pragma unroll
        for (int t = 0; t < 2; t++) {
            int c = tid + t * 256;      // 512 16B-chunks per operand tile
            int row = c >> 2, kc = c & 3;
            cpa16(aS + row * ROWB + kc * 16,
                  A + (size_t)(m0 + row) * CIN + kk + kc * 8);
            cpa16(bS + row * ROWB + kc * 16,
                  W + (size_t)(n0 + row) * CIN + kk + kc * 8);
        }
        cp_commit();
    };

    // prologue: stages 0..2 in flight
    load_stage(0);
    load_stage(1);
    load_stage(2);

#pragma unroll 1
    for (int it = 0; it < K_ITERS; it++) {
        const int rem = (K_ITERS - 1) - it;
        if (rem >= 2)      cp_wait<2>();
        else if (rem == 1) cp_wait<1>();
        else               cp_wait<0>();
        __syncthreads();   // stage `it` visible to all; everyone past compute(it-1)

        const uint32_t aS = sbase + (it & 3) * STAGE_BYTES;
        const uint32_t bS = aS + TILE_BYTES;
#pragma unroll
        for (int ks = 0; ks < 2; ks++) {       // two k16 steps per BK=32
            uint32_t a[4][4], b[4][2];
#pragma unroll
            for (int mi = 0; mi < 4; mi++)
                ldsm_x4(a[mi][0], a[mi][1], a[mi][2], a[mi][3],
                        aS + (wm + mi * 16 + (lane & 15)) * ROWB
                           + ks * 32 + (lane >> 4) * 16);
#pragma unroll
            for (int ni = 0; ni < 4; ni++) {
                int l = lane & 15;
                ldsm_x2(b[ni][0], b[ni][1],
                        bS + (wn + ni * 8 + (l & 7)) * ROWB
                           + ks * 32 + (l >> 3) * 16);
            }
#pragma unroll
            for (int mi = 0; mi < 4; mi++)
#pragma unroll
                for (int ni = 0; ni < 4; ni++)
                    mma_bf16(acc[mi][ni], a[mi], b[ni]);
        }

        // issue next load AFTER compute: WAR-safe with the single sync above
        if (it + 3 < K_ITERS) load_stage(it + 3);
    }

    // epilogue: direct float2 stores (c0,c1 -> row g; c2,c3 -> row g+8)
    const int g = lane >> 2, i2 = (lane & 3) * 2;
#pragma unroll
    for (int mi = 0; mi < 4; mi++) {
        const int row = m0 + wm + mi * 16 + g;
        float* o0 = out + (size_t)row * COUT + n0 + wn;
        float* o1 = o0 + 8 * COUT;
#pragma unroll
        for (int ni = 0; ni < 4; ni++) {
            *reinterpret_cast<float2*>(o0 + ni * 8 + i2) =
                make_float2(acc[mi][ni][0], acc[mi][ni][1]);
            *reinterpret_cast<float2*>(o1 + ni * 8 + i2) =
                make_float2(acc[mi][ni][2], acc[mi][ni][3]);
        }
    }
}

// ---------------- launch ----------------
extern "C" void kernel_launch(void* const* d_in, const int* in_sizes, int n_in,
                              void* d_out, int out_size) {
    const float* x    = (const float*)d_in[0];   // [4, 4096, CIN] fp32
    const float* vals = (const float*)d_in[1];   // [nnz] fp32
    const int*   idx  = (const int*)d_in[2];     // [2, nnz] int32
    float* out = (float*)d_out;                  // [M, COUT] fp32

    const int nnz = in_sizes[1];
    const int M   = in_sizes[0] / CIN;           // 16384

    // 1) densify + split W
    zero_W_kernel<<<(COUT * CIN / 4) / 256, 256>>>();
    scatter_W_kernel<<<(nnz + 255) / 256, 256>>>(vals, idx, nnz);
    convert_W_kernel<<<(COUT * CIN / 4) / 256, 256>>>();
    // 2) split x into bf16 hi/lo
    int n4 = (M * CIN) / 4;
    convert_A_kernel<<<(n4 + 255) / 256, 256>>>(x, n4);
    // 3) GEMM
    static int smem_set = 0;
    if (!smem_set) {
        cudaFuncSetAttribute(gemm_bf16x3_kernel,
                             cudaFuncAttributeMaxDynamicSharedMemorySize, SMEM_TOTAL);
        smem_set = 1;
    }
    dim3 grid(COUT / 128, M / 128);
    gemm_bf16x3_kernel<<<grid, 256, SMEM_TOTAL>>>(out);
}

// round 4
// speedup vs baseline: 2.5388x; 1.1866x over previous
#include <cuda_runtime.h>
#include <cuda_fp16.h>
#include <cstdint>

#define CIN  1024
#define COUT 1024
#define MAX_M 16384

// ---------------- device global scratch (allocation-free) ----------------
__device__ float  g_W[COUT * CIN];       // densified fp32 W
__device__ __half g_Whi[COUT * CIN];     // fp16 round of W
__device__ __half g_Ahi[MAX_M * CIN];    // fp16 hi of x
__device__ __half g_Alo[MAX_M * CIN];    // fp16 residual of x (exact pair)

// ---------------- PTX helpers (vanilla sm_80 features only) ----------------
__device__ __forceinline__ uint32_t smem_u32(const void* p) {
    uint32_t a;
    asm("{ .reg .u64 t; cvta.to.shared.u64 t, %1; cvt.u32.u64 %0, t; }"
        : "=r"(a) : "l"(p));
    return a;
}
__device__ __forceinline__ void cpa16(uint32_t dst, const void* src) {
    asm volatile("cp.async.cg.shared.global [%0], [%1], 16;" :: "r"(dst), "l"(src));
}
__device__ __forceinline__ void cp_commit() {
    asm volatile("cp.async.commit_group;" ::: "memory");
}
template<int N> __device__ __forceinline__ void cp_wait() {
    asm volatile("cp.async.wait_group %0;" :: "n"(N) : "memory");
}
__device__ __forceinline__ void ldsm_x4(uint32_t& r0, uint32_t& r1, uint32_t& r2,
                                        uint32_t& r3, uint32_t addr) {
    asm volatile("ldmatrix.sync.aligned.m8n8.x4.shared.b16 {%0,%1,%2,%3}, [%4];"
                 : "=r"(r0), "=r"(r1), "=r"(r2), "=r"(r3) : "r"(addr));
}
__device__ __forceinline__ void mma_f16(float* c, const uint32_t* a, const uint32_t* b) {
    asm volatile(
        "mma.sync.aligned.m16n8k16.row.col.f32.f16.f16.f32 "
        "{%0,%1,%2,%3}, {%4,%5,%6,%7}, {%8,%9}, {%0,%1,%2,%3};"
        : "+f"(c[0]), "+f"(c[1]), "+f"(c[2]), "+f"(c[3])
        : "r"(a[0]), "r"(a[1]), "r"(a[2]), "r"(a[3]), "r"(b[0]), "r"(b[1]));
}

// ---------------- preprocessing kernels ----------------
__global__ void zero_W_kernel() {
    int i = blockIdx.x * blockDim.x + threadIdx.x;
    reinterpret_cast<float4*>(g_W)[i] = make_float4(0.f, 0.f, 0.f, 0.f);
}

__global__ void scatter_W_kernel(const float* __restrict__ vals,
                                 const int* __restrict__ idx, int nnz) {
    int i = blockIdx.x * blockDim.x + threadIdx.x;
    if (i < nnz) {
        int r = idx[i];
        int c = idx[nnz + i];
        atomicAdd(&g_W[r * CIN + c], vals[i]);
    }
}

// x -> exact fp16 pair (hi + residual)
__global__ void convert_A_kernel(const float* __restrict__ x, int n4) {
    int i = blockIdx.x * blockDim.x + threadIdx.x;
    if (i >= n4) return;
    float4 v = reinterpret_cast<const float4*>(x)[i];
    __half h0 = __float2half_rn(v.x);
    __half h1 = __float2half_rn(v.y);
    __half h2 = __float2half_rn(v.z);
    __half h3 = __float2half_rn(v.w);
    __half l0 = __float2half_rn(v.x - __half2float(h0));
    __half l1 = __float2half_rn(v.y - __half2float(h1));
    __half l2 = __float2half_rn(v.z - __half2float(h2));
    __half l3 = __float2half_rn(v.w - __half2float(h3));
    __half2 H0; H0.x = h0; H0.y = h1;
    __half2 H1; H1.x = h2; H1.y = h3;
    __half2 L0; L0.x = l0; L0.y = l1;
    __half2 L1; L1.x = l2; L1.y = l3;
    reinterpret_cast<__half2*>(g_Ahi)[2 * i + 0] = H0;
    reinterpret_cast<__half2*>(g_Ahi)[2 * i + 1] = H1;
    reinterpret_cast<__half2*>(g_Alo)[2 * i + 0] = L0;
    reinterpret_cast<__half2*>(g_Alo)[2 * i + 1] = L1;
}

// W -> fp16 (single rounding; the only precision loss in the whole pipeline)
__global__ void convert_W_kernel() {
    int i = blockIdx.x * blockDim.x + threadIdx.x;   // COUT*CIN/4 threads
    float4 v = reinterpret_cast<const float4*>(g_W)[i];
    __half2 H0; H0.x = __float2half_rn(v.x); H0.y = __float2half_rn(v.y);
    __half2 H1; H1.x = __float2half_rn(v.z); H1.y = __float2half_rn(v.w);
    reinterpret_cast<__half2*>(g_Whi)[2 * i + 0] = H0;
    reinterpret_cast<__half2*>(g_Whi)[2 * i + 1] = H1;
}

// ---------------- fp16 mma.sync GEMM, 2 K-passes ----------------
// out[m,n] = sum_k Ahi[m,k]*Whi[n,k]  +  sum_k Alo[m,k]*Whi[n,k]
// CTA tile BM=128 x BN=256, BK=32. 256 thr = 8 warps in 2(M)x4(N); warp 64x64.
#define BM 128
#define BN 256
#define BK 32
#define ROWB 80                         // 64B data + 16B pad per k-row
#define A_TILE_BYTES (BM * ROWB)        // 10240
#define B_TILE_BYTES (BN * ROWB)        // 20480
#define STAGE_BYTES (A_TILE_BYTES + B_TILE_BYTES)
#define NSTAGE 4
#define SMEM_TOTAL (NSTAGE * STAGE_BYTES)   // 122880
#define K_ITERS 64                      // 2 phases * (1024/32)

__global__ void __launch_bounds__(256)
gemm_f16x2_kernel(float* __restrict__ out) {
    extern __shared__ char smem_raw[];
    const uint32_t sbase = smem_u32(smem_raw);
    const int tid  = threadIdx.x;
    const int lane = tid & 31;
    const int wid  = tid >> 5;
    const int wm   = (wid & 1) * 64;    // warp M offset
    const int wn   = (wid >> 1) * 64;   // warp N offset
    const int m0   = blockIdx.y * BM;
    const int n0   = blockIdx.x * BN;

    float acc[4][8][4];
#pragma unroll
    for (int mi = 0; mi < 4; mi++)
#pragma unroll
        for (int ni = 0; ni < 8; ni++)
#pragma unroll
            for (int q = 0; q < 4; q++) acc[mi][ni][q] = 0.f;

    auto load_stage = [&](int j) {
        const int ph = j >> 5;                  // 0: Ahi, 1: Alo
        const int kk = (j & 31) * BK;
        const __half* A = ph ? g_Alo : g_Ahi;
        const uint32_t aS = sbase + (j & 3) * STAGE_BYTES;
        const uint32_t bS = aS + A_TILE_BYTES;
        // A: 128 rows x 4 x 16B = 512 chunks
#pragma unroll
        for (int t = 0; t < 2; t++) {
            int c = tid + t * 256;
            int row = c >> 2, kc = c & 3;
            cpa16(aS + row * ROWB + kc * 16,
                  A + (size_t)(m0 + row) * CIN + kk + kc * 8);
        }
        // B (Whi): 256 rows x 4 x 16B = 1024 chunks
#pragma unroll
        for (int t = 0; t < 4; t++) {
            int c = tid + t * 256;
            int row = c >> 2, kc = c & 3;
            cpa16(bS + row * ROWB + kc * 16,
                  g_Whi + (size_t)(n0 + row) * CIN + kk + kc * 8);
        }
        cp_commit();
    };

    load_stage(0);
    load_stage(1);
    load_stage(2);

#pragma unroll 1
    for (int it = 0; it < K_ITERS; it++) {
        const int rem = (K_ITERS - 1) - it;
        if (rem >= 2)      cp_wait<2>();
        else if (rem == 1) cp_wait<1>();
        else               cp_wait<0>();
        __syncthreads();

        const uint32_t aS = sbase + (it & 3) * STAGE_BYTES;
        const uint32_t bS = aS + A_TILE_BYTES;
#pragma unroll
        for (int ks = 0; ks < 2; ks++) {       // two k16 steps per BK=32
            uint32_t a[4][4], b[8][2];
#pragma unroll
            for (int mi = 0; mi < 4; mi++)
                ldsm_x4(a[mi][0], a[mi][1], a[mi][2], a[mi][3],
                        aS + (wm + mi * 16 + (lane & 15)) * ROWB
                           + ks * 32 + (lane >> 4) * 16);
#pragma unroll
            for (int pr = 0; pr < 4; pr++) {
                // x4: tiles (n+0..7,k0),(n+0..7,k8),(n+8..15,k0),(n+8..15,k8)
                int t = lane >> 3;
                int row = wn + pr * 16 + ((t >> 1) << 3) + (lane & 7);
                ldsm_x4(b[2 * pr][0], b[2 * pr][1],
                        b[2 * pr + 1][0], b[2 * pr + 1][1],
                        bS + row * ROWB + ks * 32 + (t & 1) * 16);
            }
#pragma unroll
            for (int mi = 0; mi < 4; mi++)
#pragma unroll
                for (int ni = 0; ni < 8; ni++)
                    mma_f16(acc[mi][ni], a[mi], b[ni]);
        }

        if (it + 3 < K_ITERS) load_stage(it + 3);
    }

    // epilogue: float2 direct stores
    const int g = lane >> 2, i2 = (lane & 3) * 2;
#pragma unroll
    for (int mi = 0; mi < 4; mi++) {
        const int row = m0 + wm + mi * 16 + g;
        float* o0 = out + (size_t)row * COUT + n0 + wn;
        float* o1 = o0 + 8 * COUT;
#pragma unroll
        for (int ni = 0; ni < 8; ni++) {
            *reinterpret_cast<float2*>(o0 + ni * 8 + i2) =
                make_float2(acc[mi][ni][0], acc[mi][ni][1]);
            *reinterpret_cast<float2*>(o1 + ni * 8 + i2) =
                make_float2(acc[mi][ni][2], acc[mi][ni][3]);
        }
    }
}

// ---------------- launch ----------------
extern "C" void kernel_launch(void* const* d_in, const int* in_sizes, int n_in,
                              void* d_out, int out_size) {
    const float* x    = (const float*)d_in[0];   // [4, 4096, CIN] fp32
    const float* vals = (const float*)d_in[1];   // [nnz] fp32
    const int*   idx  = (const int*)d_in[2];     // [2, nnz] int32
    float* out = (float*)d_out;                  // [M, COUT] fp32

    const int nnz = in_sizes[1];
    const int M   = in_sizes[0] / CIN;           // 16384

    zero_W_kernel<<<(COUT * CIN / 4) / 256, 256>>>();
    scatter_W_kernel<<<(nnz + 255) / 256, 256>>>(vals, idx, nnz);
    convert_W_kernel<<<(COUT * CIN / 4) / 256, 256>>>();
    int n4 = (M * CIN) / 4;
    convert_A_kernel<<<(n4 + 255) / 256, 256>>>(x, n4);

    static int smem_set = 0;
    if (!smem_set) {
        cudaFuncSetAttribute(gemm_f16x2_kernel,
                             cudaFuncAttributeMaxDynamicSharedMemorySize, SMEM_TOTAL);
        smem_set = 1;
    }
    dim3 grid(COUT / BN, M / BM);
    gemm_f16x2_kernel<<<grid, 256, SMEM_TOTAL>>>(out);
}

// round 5
// speedup vs baseline: 5.1271x; 2.0195x over previous
#include <cuda_runtime.h>
#include <cuda_fp16.h>
#include <cstdint>

#define CIN  1024
#define COUT 1024
#define MAX_M 16384

// ---------------- device global scratch (allocation-free) ----------------
__device__ float  g_W[COUT * CIN];       // densified fp32 W
__device__ __half g_Whi[COUT * CIN];     // fp16 round of W
__device__ __half g_Ahi[MAX_M * CIN];    // fp16 round of x

// ---------------- PTX helpers (vanilla sm_80 features only) ----------------
__device__ __forceinline__ uint32_t smem_u32(const void* p) {
    uint32_t a;
    asm("{ .reg .u64 t; cvta.to.shared.u64 t, %1; cvt.u32.u64 %0, t; }"
        : "=r"(a) : "l"(p));
    return a;
}
__device__ __forceinline__ void cpa16(uint32_t dst, const void* src) {
    asm volatile("cp.async.cg.shared.global [%0], [%1], 16;" :: "r"(dst), "l"(src));
}
__device__ __forceinline__ void cp_commit() {
    asm volatile("cp.async.commit_group;" ::: "memory");
}
template<int N> __device__ __forceinline__ void cp_wait() {
    asm volatile("cp.async.wait_group %0;" :: "n"(N) : "memory");
}
__device__ __forceinline__ void ldsm_x4(uint32_t& r0, uint32_t& r1, uint32_t& r2,
                                        uint32_t& r3, uint32_t addr) {
    asm volatile("ldmatrix.sync.aligned.m8n8.x4.shared.b16 {%0,%1,%2,%3}, [%4];"
                 : "=r"(r0), "=r"(r1), "=r"(r2), "=r"(r3) : "r"(addr));
}
__device__ __forceinline__ void mma_f16(float* c, const uint32_t* a, const uint32_t* b) {
    asm volatile(
        "mma.sync.aligned.m16n8k16.row.col.f32.f16.f16.f32 "
        "{%0,%1,%2,%3}, {%4,%5,%6,%7}, {%8,%9}, {%0,%1,%2,%3};"
        : "+f"(c[0]), "+f"(c[1]), "+f"(c[2]), "+f"(c[3])
        : "r"(a[0]), "r"(a[1]), "r"(a[2]), "r"(a[3]), "r"(b[0]), "r"(b[1]));
}

// ---------------- preprocessing kernels ----------------
__global__ void zero_W_kernel() {
    int i = blockIdx.x * blockDim.x + threadIdx.x;
    reinterpret_cast<float4*>(g_W)[i] = make_float4(0.f, 0.f, 0.f, 0.f);
}

__global__ void scatter_W_kernel(const float* __restrict__ vals,
                                 const int* __restrict__ idx, int nnz) {
    int i = blockIdx.x * blockDim.x + threadIdx.x;
    if (i < nnz) {
        int r = idx[i];
        int c = idx[nnz + i];
        atomicAdd(&g_W[r * CIN + c], vals[i]);
    }
}

__global__ void convert_A_kernel(const float* __restrict__ x, int n4) {
    int i = blockIdx.x * blockDim.x + threadIdx.x;
    if (i >= n4) return;
    float4 v = reinterpret_cast<const float4*>(x)[i];
    __half2 H0; H0.x = __float2half_rn(v.x); H0.y = __float2half_rn(v.y);
    __half2 H1; H1.x = __float2half_rn(v.z); H1.y = __float2half_rn(v.w);
    reinterpret_cast<__half2*>(g_Ahi)[2 * i + 0] = H0;
    reinterpret_cast<__half2*>(g_Ahi)[2 * i + 1] = H1;
}

__global__ void convert_W_kernel() {
    int i = blockIdx.x * blockDim.x + threadIdx.x;   // COUT*CIN/4 threads
    float4 v = reinterpret_cast<const float4*>(g_W)[i];
    __half2 H0; H0.x = __float2half_rn(v.x); H0.y = __float2half_rn(v.y);
    __half2 H1; H1.x = __float2half_rn(v.z); H1.y = __float2half_rn(v.w);
    reinterpret_cast<__half2*>(g_Whi)[2 * i + 0] = H0;
    reinterpret_cast<__half2*>(g_Whi)[2 * i + 1] = H1;
}

// ---------------- fp16 mma.sync GEMM, single pass ----------------
// out[m,n] = sum_k Ahi[m,k] * Whi[n,k]
// BM=BN=128, BK=32. 256 thr = 8 warps in 2(M)x4(N); warp tile 64x32.
// 2 CTAs/SM (smem 80KB, ~110 regs/thr).
#define BK 32
#define ROWB 80                 // 64B data + 16B pad per k-row
#define TILE_BYTES (128 * ROWB) // 10240 per operand
#define STAGE_BYTES (2 * TILE_BYTES)
#define NSTAGE 4
#define SMEM_TOTAL (NSTAGE * STAGE_BYTES)   // 81920
#define K_ITERS 32              // 1024 / 32

__global__ void __launch_bounds__(256, 2)
gemm_f16_kernel(float* __restrict__ out) {
    extern __shared__ char smem_raw[];
    const uint32_t sbase = smem_u32(smem_raw);
    const int tid  = threadIdx.x;
    const int lane = tid & 31;
    const int wid  = tid >> 5;
    const int wm   = (wid & 1) * 64;   // warp M offset
    const int wn   = (wid >> 1) * 32;  // warp N offset
    const int m0   = blockIdx.y * 128;
    const int n0   = blockIdx.x * 128;

    float acc[4][4][4];
#pragma unroll
    for (int mi = 0; mi < 4; mi++)
#pragma unroll
        for (int ni = 0; ni < 4; ni++)
#pragma unroll
            for (int q = 0; q < 4; q++) acc[mi][ni][q] = 0.f;

    auto load_stage = [&](int j) {
        const int kk = j * BK;
        const uint32_t aS = sbase + (j & 3) * STAGE_BYTES;
        const uint32_t bS = aS + TILE_BYTES;
#pragma unroll
        for (int t = 0; t < 2; t++) {
            int c = tid + t * 256;      // 512 16B-chunks per operand tile
            int row = c >> 2, kc = c & 3;
            cpa16(aS + row * ROWB + kc * 16,
                  g_Ahi + (size_t)(m0 + row) * CIN + kk + kc * 8);
            cpa16(bS + row * ROWB + kc * 16,
                  g_Whi + (size_t)(n0 + row) * CIN + kk + kc * 8);
        }
        cp_commit();
    };

    load_stage(0);
    load_stage(1);
    load_stage(2);

#pragma unroll 1
    for (int it = 0; it < K_ITERS; it++) {
        const int rem = (K_ITERS - 1) - it;
        if (rem >= 2)      cp_wait<2>();
        else if (rem == 1) cp_wait<1>();
        else               cp_wait<0>();
        __syncthreads();

        const uint32_t aS = sbase + (it & 3) * STAGE_BYTES;
        const uint32_t bS = aS + TILE_BYTES;
#pragma unroll
        for (int ks = 0; ks < 2; ks++) {       // two k16 steps per BK=32
            uint32_t a[4][4], b[4][2];
#pragma unroll
            for (int mi = 0; mi < 4; mi++)
                ldsm_x4(a[mi][0], a[mi][1], a[mi][2], a[mi][3],
                        aS + (wm + mi * 16 + (lane & 15)) * ROWB
                           + ks * 32 + (lane >> 4) * 16);
            // B: two ldmatrix.x4, each covers 16 n-rows x full k16
#pragma unroll
            for (int pr = 0; pr < 2; pr++) {
                int t = lane >> 3;
                int row = wn + pr * 16 + ((t >> 1) << 3) + (lane & 7);
                ldsm_x4(b[2 * pr][0], b[2 * pr][1],
                        b[2 * pr + 1][0], b[2 * pr + 1][1],
                        bS + row * ROWB + ks * 32 + (t & 1) * 16);
            }
#pragma unroll
            for (int mi = 0; mi < 4; mi++)
#pragma unroll
                for (int ni = 0; ni < 4; ni++)
                    mma_f16(acc[mi][ni], a[mi], b[ni]);
        }

        if (it + 3 < K_ITERS) load_stage(it + 3);
    }

    // epilogue: direct float2 stores
    const int g = lane >> 2, i2 = (lane & 3) * 2;
#pragma unroll
    for (int mi = 0; mi < 4; mi++) {
        const int row = m0 + wm + mi * 16 + g;
        float* o0 = out + (size_t)row * COUT + n0 + wn;
        float* o1 = o0 + 8 * COUT;
#pragma unroll
        for (int ni = 0; ni < 4; ni++) {
            *reinterpret_cast<float2*>(o0 + ni * 8 + i2) =
                make_float2(acc[mi][ni][0], acc[mi][ni][1]);
            *reinterpret_cast<float2*>(o1 + ni * 8 + i2) =
                make_float2(acc[mi][ni][2], acc[mi][ni][3]);
        }
    }
}

// ---------------- launch ----------------
extern "C" void kernel_launch(void* const* d_in, const int* in_sizes, int n_in,
                              void* d_out, int out_size) {
    const float* x    = (const float*)d_in[0];   // [4, 4096, CIN] fp32
    const float* vals = (const float*)d_in[1];   // [nnz] fp32
    const int*   idx  = (const int*)d_in[2];     // [2, nnz] int32
    float* out = (float*)d_out;                  // [M, COUT] fp32

    const int nnz = in_sizes[1];
    const int M   = in_sizes[0] / CIN;           // 16384

    zero_W_kernel<<<(COUT * CIN / 4) / 256, 256>>>();
    scatter_W_kernel<<<(nnz + 255) / 256, 256>>>(vals, idx, nnz);
    convert_W_kernel<<<(COUT * CIN / 4) / 256, 256>>>();
    int n4 = (M * CIN) / 4;
    convert_A_kernel<<<(n4 + 255) / 256, 256>>>(x, n4);

    static int smem_set = 0;
    if (!smem_set) {
        cudaFuncSetAttribute(gemm_f16_kernel,
                             cudaFuncAttributeMaxDynamicSharedMemorySize, SMEM_TOTAL);
        smem_set = 1;
    }
    dim3 grid(COUT / 128, M / 128);
    gemm_f16_kernel<<<grid, 256, SMEM_TOTAL>>>(out);
}

// round 6
// speedup vs baseline: 5.6366x; 1.0994x over previous
#include <cuda_runtime.h>
#include <cuda_fp16.h>
#include <cstdint>

#define CIN  1024
#define COUT 1024
#define MAX_M 16384

// ---------------- device global scratch (allocation-free) ----------------
__device__ float  g_W[COUT * CIN];       // densified fp32 W
__device__ __half g_Whi[COUT * CIN];     // fp16 round of W
__device__ __half g_Ahi[MAX_M * CIN];    // fp16 round of x

// ---------------- PTX helpers (vanilla sm_80 features only) ----------------
__device__ __forceinline__ uint32_t smem_u32(const void* p) {
    uint32_t a;
    asm("{ .reg .u64 t; cvta.to.shared.u64 t, %1; cvt.u32.u64 %0, t; }"
        : "=r"(a) : "l"(p));
    return a;
}
__device__ __forceinline__ void cpa16(uint32_t dst, const void* src) {
    asm volatile("cp.async.cg.shared.global [%0], [%1], 16;" :: "r"(dst), "l"(src));
}
__device__ __forceinline__ void cp_commit() {
    asm volatile("cp.async.commit_group;" ::: "memory");
}
template<int N> __device__ __forceinline__ void cp_wait() {
    asm volatile("cp.async.wait_group %0;" :: "n"(N) : "memory");
}
__device__ __forceinline__ void ldsm_x4(uint32_t& r0, uint32_t& r1, uint32_t& r2,
                                        uint32_t& r3, uint32_t addr) {
    asm volatile("ldmatrix.sync.aligned.m8n8.x4.shared.b16 {%0,%1,%2,%3}, [%4];"
                 : "=r"(r0), "=r"(r1), "=r"(r2), "=r"(r3) : "r"(addr));
}
__device__ __forceinline__ void mma_f16(float* c, const uint32_t* a, const uint32_t* b) {
    asm volatile(
        "mma.sync.aligned.m16n8k16.row.col.f32.f16.f16.f32 "
        "{%0,%1,%2,%3}, {%4,%5,%6,%7}, {%8,%9}, {%0,%1,%2,%3};"
        : "+f"(c[0]), "+f"(c[1]), "+f"(c[2]), "+f"(c[3])
        : "r"(a[0]), "r"(a[1]), "r"(a[2]), "r"(a[3]), "r"(b[0]), "r"(b[1]));
}

// ---------------- preprocessing kernels ----------------
__global__ void zero_W_kernel() {
    int i = blockIdx.x * blockDim.x + threadIdx.x;
    reinterpret_cast<float4*>(g_W)[i] = make_float4(0.f, 0.f, 0.f, 0.f);
}

__global__ void scatter_W_kernel(const float* __restrict__ vals,
                                 const int* __restrict__ idx, int nnz) {
    int i = blockIdx.x * blockDim.x + threadIdx.x;
    if (i < nnz) {
        int r = idx[i];
        int c = idx[nnz + i];
        atomicAdd(&g_W[r * CIN + c], vals[i]);
    }
}

// Fused fp32->fp16 conversion for A (from x) and W (from g_W).
// 8 floats per thread: 2 float4 loads -> 1 uint4 (8 halves) store.
__global__ void convert_AW_kernel(const float* __restrict__ x, int nA8) {
    int i = blockIdx.x * blockDim.x + threadIdx.x;
    const float4* src;
    __half* dst;
    int j;
    if (i < nA8) { src = reinterpret_cast<const float4*>(x); dst = g_Ahi; j = i; }
    else         { src = reinterpret_cast<const float4*>(g_W); dst = g_Whi; j = i - nA8; }
    float4 v0 = src[2 * j + 0];
    float4 v1 = src[2 * j + 1];
    __half2 h0 = __float22half2_rn(make_float2(v0.x, v0.y));
    __half2 h1 = __float22half2_rn(make_float2(v0.z, v0.w));
    __half2 h2 = __float22half2_rn(make_float2(v1.x, v1.y));
    __half2 h3 = __float22half2_rn(make_float2(v1.z, v1.w));
    uint4 o;
    o.x = *reinterpret_cast<uint32_t*>(&h0);
    o.y = *reinterpret_cast<uint32_t*>(&h1);
    o.z = *reinterpret_cast<uint32_t*>(&h2);
    o.w = *reinterpret_cast<uint32_t*>(&h3);
    reinterpret_cast<uint4*>(dst)[j] = o;
}

// ---------------- fp16 mma.sync GEMM, single pass ----------------
// out[m,n] = sum_k Ahi[m,k] * Whi[n,k]
// BM=BN=128, BK=64. 256 thr = 8 warps in 2(M)x4(N); warp tile 64x32.
// ROWB=144 (128B data + 16B pad): stride mod 128 = 16 -> conflict-free
// ldmatrix AND cp.async STS. NSTAGE=3 -> 110.6KB smem, 2 CTAs/SM.
#define BK 64
#define ROWB 144
#define TILE_BYTES (128 * ROWB)          // 18432 per operand
#define STAGE_BYTES (2 * TILE_BYTES)     // 36864
#define NSTAGE 3
#define SMEM_TOTAL (NSTAGE * STAGE_BYTES)   // 110592
#define K_ITERS 16                       // 1024 / 64

__global__ void __launch_bounds__(256, 2)
gemm_f16_kernel(float* __restrict__ out) {
    extern __shared__ char smem_raw[];
    const uint32_t sbase = smem_u32(smem_raw);
    const int tid  = threadIdx.x;
    const int lane = tid & 31;
    const int wid  = tid >> 5;
    const int wm   = (wid & 1) * 64;   // warp M offset
    const int wn   = (wid >> 1) * 32;  // warp N offset
    const int m0   = blockIdx.y * 128;
    const int n0   = blockIdx.x * 128;

    float acc[4][4][4];
#pragma unroll
    for (int mi = 0; mi < 4; mi++)
#pragma unroll
        for (int ni = 0; ni < 4; ni++)
#pragma unroll
            for (int q = 0; q < 4; q++) acc[mi][ni][q] = 0.f;

    // stage buffer index: j % 3
    auto load_stage = [&](int j) {
        const int kk = j * BK;
        const uint32_t aS = sbase + (j % NSTAGE) * STAGE_BYTES;
        const uint32_t bS = aS + TILE_BYTES;
        // each operand: 128 rows x 8 x 16B = 1024 chunks; 4 per thread
#pragma unroll
        for (int t = 0; t < 4; t++) {
            int c = tid + t * 256;
            int row = c >> 3, kc = c & 7;
            cpa16(aS + row * ROWB + kc * 16,
                  g_Ahi + (size_t)(m0 + row) * CIN + kk + kc * 8);
            cpa16(bS + row * ROWB + kc * 16,
                  g_Whi + (size_t)(n0 + row) * CIN + kk + kc * 8);
        }
        cp_commit();
    };

    load_stage(0);
    load_stage(1);

#pragma unroll 1
    for (int it = 0; it < K_ITERS; it++) {
        if (it == K_ITERS - 1) cp_wait<0>();
        else                   cp_wait<1>();
        __syncthreads();
        // issue next load ASAP (overwrites buffer of iter it-1; all threads
        // passed the sync above, so compute(it-1) is complete everywhere)
        if (it + 2 < K_ITERS) load_stage(it + 2);

        const uint32_t aS = sbase + (it % NSTAGE) * STAGE_BYTES;
        const uint32_t bS = aS + TILE_BYTES;
#pragma unroll
        for (int ks = 0; ks < 4; ks++) {       // four k16 steps per BK=64
            uint32_t a[4][4], b[4][2];
#pragma unroll
            for (int mi = 0; mi < 4; mi++)
                ldsm_x4(a[mi][0], a[mi][1], a[mi][2], a[mi][3],
                        aS + (wm + mi * 16 + (lane & 15)) * ROWB
                           + ks * 32 + (lane >> 4) * 16);
#pragma unroll
            for (int pr = 0; pr < 2; pr++) {
                int t = lane >> 3;
                int row = wn + pr * 16 + ((t >> 1) << 3) + (lane & 7);
                ldsm_x4(b[2 * pr][0], b[2 * pr][1],
                        b[2 * pr + 1][0], b[2 * pr + 1][1],
                        bS + row * ROWB + ks * 32 + (t & 1) * 16);
            }
#pragma unroll
            for (int mi = 0; mi < 4; mi++)
#pragma unroll
                for (int ni = 0; ni < 4; ni++)
                    mma_f16(acc[mi][ni], a[mi], b[ni]);
        }
    }

    // epilogue: direct float2 stores
    const int g = lane >> 2, i2 = (lane & 3) * 2;
#pragma unroll
    for (int mi = 0; mi < 4; mi++) {
        const int row = m0 + wm + mi * 16 + g;
        float* o0 = out + (size_t)row * COUT + n0 + wn;
        float* o1 = o0 + 8 * COUT;
#pragma unroll
        for (int ni = 0; ni < 4; ni++) {
            *reinterpret_cast<float2*>(o0 + ni * 8 + i2) =
                make_float2(acc[mi][ni][0], acc[mi][ni][1]);
            *reinterpret_cast<float2*>(o1 + ni * 8 + i2) =
                make_float2(acc[mi][ni][2], acc[mi][ni][3]);
        }
    }
}

// ---------------- launch ----------------
extern "C" void kernel_launch(void* const* d_in, const int* in_sizes, int n_in,
                              void* d_out, int out_size) {
    const float* x    = (const float*)d_in[0];   // [4, 4096, CIN] fp32
    const float* vals = (const float*)d_in[1];   // [nnz] fp32
    const int*   idx  = (const int*)d_in[2];     // [2, nnz] int32
    float* out = (float*)d_out;                  // [M, COUT] fp32

    const int nnz = in_sizes[1];
    const int M   = in_sizes[0] / CIN;           // 16384

    zero_W_kernel<<<(COUT * CIN / 4) / 256, 256>>>();
    scatter_W_kernel<<<(nnz + 255) / 256, 256>>>(vals, idx, nnz);

    const int nA8 = (M * CIN) / 8;
    const int nW8 = (COUT * CIN) / 8;
    convert_AW_kernel<<<(nA8 + nW8 + 255) / 256, 256>>>(x, nA8);

    static int smem_set = 0;
    if (!smem_set) {
        cudaFuncSetAttribute(gemm_f16_kernel,
                             cudaFuncAttributeMaxDynamicSharedMemorySize, SMEM_TOTAL);
        smem_set = 1;
    }
    dim3 grid(COUT / 128, M / 128);
    gemm_f16_kernel<<<grid, 256, SMEM_TOTAL>>>(out);
}